// round 14
// baseline (speedup 1.0000x reference)
#include <cuda_runtime.h>
#include <cstdint>

#define N_BITS 108
#define N_OUT  7
#define TPB    256

// Row = 108 floats = 432 B = 27 uint4. Values exactly 0.0f/1.0f:
// (word >> 29) & 1 extracts the bit.
//
// Quantitative line model (validated on R13: predicted 674 MB, measured 677):
// DRAM cost = distinct 128 B lines touched; dur = bytes / ~6.15 TB/s.
// Row-aligned reads waste 1.875 lines per 128 B head. Fix: every round reads
// exactly ONE whole aligned 128 B line of the window a0 = (27*row) & ~7,
// junk prefix (4d bits, d = (27*row)&7) masked off. E[lines/row] ~ 1.92
// -> ~548 MB total vs R9's 586.
// Rounds: line0 | line1 | line2 | line3(clamped) | line4 (only d>=6, clamped).

__device__ __forceinline__ unsigned mask4(uint4 w) {
    return ((w.x >> 29) & 1u)
         | (((w.y >> 29) & 1u) << 1)
         | (((w.z >> 29) & 1u) << 2)
         | (((w.w >> 29) & 1u) << 3);
}

__global__ __launch_bounds__(TPB, 8)
void lzd108_kernel(const uint4* __restrict__ X, float* __restrict__ out,
                   int n_rows, unsigned lim /* total uint4 count */) {
    __shared__ unsigned short s_pos[TPB];

    int tid = threadIdx.x;
    size_t brow = (size_t)blockIdx.x * TPB;
    int row = (int)brow + tid;
    int pos = N_BITS;  // 108 = 1101100b == LZC_108 (all-zero row)

    if (row < n_rows) {
        unsigned w0 = 27u * (unsigned)row;   // uint4 index of row start
        unsigned a0 = w0 & ~7u;              // 128B-line-aligned window base
        int d = (int)(w0 & 7u);              // junk uint4 words (0..7)
        int jb = 4 * d;                      // junk bits
        unsigned last = lim - 1u;
        const uint4* p = X + a0;

        int pw = -1;  // first-one in WINDOW bits; row pos = pw - jb

        // Round 0: line 0 — window words [0,8), row bits [0, 32-jb)
        unsigned m = 0;
        #pragma unroll
        for (int j = 0; j < 8; ++j) m |= mask4(__ldg(p + j)) << (4 * j);
        m &= 0xFFFFFFFFu << jb;              // drop previous-row junk
        if (m) {
            pw = __ffs(m) - 1;
        } else {
            // Round 1: line 1 — words [8,16)
            m = 0;
            #pragma unroll
            for (int j = 0; j < 8; ++j) m |= mask4(__ldg(p + 8 + j)) << (4 * j);
            if (m) {
                pw = 32 + __ffs(m) - 1;
            } else {
                // Round 2: line 2 — words [16,24)
                m = 0;
                #pragma unroll
                for (int j = 0; j < 8; ++j) m |= mask4(__ldg(p + 16 + j)) << (4 * j);
                if (m) {
                    pw = 64 + __ffs(m) - 1;
                } else {
                    // Round 3: line 3 — words [24,32), clamped at buffer end.
                    // Valid window words: idx < d + 27 -> count = min(8, d+3).
                    m = 0;
                    #pragma unroll
                    for (int j = 0; j < 8; ++j) {
                        unsigned gi = a0 + 24 + j;
                        m |= mask4(__ldg(X + min(gi, last))) << (4 * j);
                    }
                    int v3 = d + 3;                    // 3..10
                    m &= (v3 >= 8) ? 0xFFFFFFFFu : ((1u << (4 * v3)) - 1u);
                    if (m) {
                        pw = 96 + __ffs(m) - 1;
                    } else if (d >= 6) {
                        // Round 4: line 4 — words [32,40), valid = d-5 (1..2)
                        m = 0;
                        #pragma unroll
                        for (int j = 0; j < 8; ++j) {
                            unsigned gi = a0 + 32 + j;
                            m |= mask4(__ldg(X + min(gi, last))) << (4 * j);
                        }
                        m &= (1u << (4 * (d - 5))) - 1u;
                        if (m) pw = 128 + __ffs(m) - 1;
                    }
                }
            }
        }
        if (pw >= 0) pos = pw - jb;
    }

    s_pos[tid] = (unsigned short)pos;
    __syncthreads();

    // Coalesced output: block writes its 1792 floats contiguously,
    // reconstructing bits from s_pos.
    size_t ob = brow * N_OUT;
    size_t total = (size_t)n_rows * N_OUT;
    #pragma unroll
    for (int i = 0; i < N_OUT; ++i) {
        size_t gi = ob + (size_t)(i * TPB + tid);
        if (gi < total) {
            int local = i * TPB + tid;   // 0..1791
            int r = local / N_OUT;
            int b = local - r * N_OUT;
            out[gi] = (float)((s_pos[r] >> (6 - b)) & 1);
        }
    }
}

extern "C" void kernel_launch(void* const* d_in, const int* in_sizes, int n_in,
                              void* d_out, int out_size) {
    const uint4* X = (const uint4*)d_in[0];
    float* out = (float*)d_out;
    int n_rows = in_sizes[0] / N_BITS;
    unsigned lim = (unsigned)(in_sizes[0] / 4);  // total uint4 count

    int blocks = (n_rows + TPB - 1) / TPB;
    lzd108_kernel<<<blocks, TPB>>>(X, out, n_rows, lim);
}

// round 15
// speedup vs baseline: 1.0882x; 1.0882x over previous
#include <cuda_runtime.h>
#include <cstdint>

#define N_BITS 108
#define N_OUT  7
#define TPB    256
#define NWARPS (TPB / 32)

// Row = 108 floats = 432 B = 27 uint4. Values exactly 0.0f/1.0f:
// (word >> 29) & 1 extracts the bit.
// Model (validated R5-R14): dur = max(DRAM bytes/6.15TB/s, lane-loads*L1 rate).
// Phase 1: row-per-thread head, words 0..7 (128 B) -> resolves 62%.
// Phase 2 (mid-drain): queued rows, words 8..15 only — 4 rows per warp
//   instruction (8 lanes/row), software-pipelined; resolves 62% of queue.
// Phase 3 (tail-drain): survivors (14% of rows), words 16..26 — 2 rows per
//   warp instruction (11 of 16 lanes/row).
// vs R7: saves ~176 B for the 23.5% of rows that queue but resolve mid.

__device__ __forceinline__ unsigned mask4(uint4 w) {
    return ((w.x >> 29) & 1u)
         | (((w.y >> 29) & 1u) << 1)
         | (((w.z >> 29) & 1u) << 2)
         | (((w.w >> 29) & 1u) << 3);
}

__global__ __launch_bounds__(TPB, 8)
void lzd108_kernel(const uint4* __restrict__ X, float* __restrict__ out, int n_rows) {
    __shared__ unsigned short s_pos[TPB];
    __shared__ unsigned short s_q[TPB];
    __shared__ unsigned short s_q2[TPB];
    __shared__ int s_cnt, s_cnt2;

    int tid = threadIdx.x;
    if (tid == 0) { s_cnt = 0; s_cnt2 = 0; }
    __syncthreads();

    size_t brow = (size_t)blockIdx.x * TPB;
    int row = (int)brow + tid;
    int pos = N_BITS;  // 108 = 1101100b == LZC_108 (all-zero row)

    if (row < n_rows) {
        const uint4* p = X + (size_t)row * 27;
        // Phase 1: bits [0,32) — words 0..7, 8 independent LDG.128
        unsigned m = 0;
        #pragma unroll
        for (int j = 0; j < 8; ++j) m |= mask4(__ldg(p + j)) << (4 * j);
        if (m) pos = __ffs(m) - 1;
        else   s_q[atomicAdd(&s_cnt, 1)] = (unsigned short)tid;
    }
    s_pos[tid] = (unsigned short)pos;
    __syncthreads();

    int nq = s_cnt;
    int lane = tid & 31;
    int wid = tid >> 5;

    // Phase 2: mid-drain — bits [32,64) = words 8..15.
    // 4 rows/iteration: lane group g = lane>>3 handles queue slot base+g,
    // li = lane&7 loads word 8+li. Pipelined one iteration deep.
    {
        int g = lane >> 3, li = lane & 7;
        int base = 4 * wid;
        int slot = base + g;
        int t = -1;
        unsigned mym = 0;
        if (base < nq && slot < nq) {
            t = s_q[slot];
            mym = mask4(__ldg(X + (brow + (size_t)t) * 27 + 8 + li));
        }
        while (base < nq) {
            int nbase = base + 4 * NWARPS;
            int nslot = nbase + g;
            int nt = -1;
            unsigned nm = 0;
            if (nbase < nq && nslot < nq) {           // prefetch next iter
                nt = s_q[nslot];
                nm = mask4(__ldg(X + (brow + (size_t)nt) * 27 + 8 + li));
            }
            unsigned bal = __ballot_sync(0xFFFFFFFFu, mym != 0u);
            unsigned grp = (bal >> (8 * g)) & 0xFFu;
            int fl = __ffs(grp) - 1;                  // -1 if group empty
            unsigned wm = __shfl_sync(0xFFFFFFFFu, mym, 8 * g + (fl < 0 ? 0 : fl));
            if (slot < nq && li == 0) {
                if (grp) s_pos[t] = (unsigned short)(32 + 4 * fl + __ffs(wm) - 1);
                else     s_q2[atomicAdd(&s_cnt2, 1)] = (unsigned short)t;
            }
            base = nbase; slot = nslot; t = nt; mym = nm;
        }
    }
    __syncthreads();

    // Phase 3: tail-drain — bits [64,108) = words 16..26 (11 uint4).
    // 2 rows/iteration: g2 = lane>>4, li2 = lane&15 (active li2 < 11).
    {
        int nq2 = s_cnt2;
        int g2 = lane >> 4, li2 = lane & 15;
        for (int base = 2 * wid; base < nq2; base += 2 * NWARPS) {
            int slot = base + g2;
            int t = -1;
            unsigned mym = 0;
            if (slot < nq2) {
                t = s_q2[slot];
                if (li2 < 11)
                    mym = mask4(__ldg(X + (brow + (size_t)t) * 27 + 16 + li2));
            }
            unsigned bal = __ballot_sync(0xFFFFFFFFu, mym != 0u);
            unsigned grp = (bal >> (16 * g2)) & 0x7FFu;
            int fl = __ffs(grp) - 1;
            unsigned wm = __shfl_sync(0xFFFFFFFFu, mym, 16 * g2 + (fl < 0 ? 0 : fl));
            if (slot < nq2 && li2 == 0 && grp)
                s_pos[t] = (unsigned short)(64 + 4 * fl + __ffs(wm) - 1);
            // group empty -> all-zero row, stays 108
        }
    }
    __syncthreads();

    // Coalesced output: block writes its 1792 floats contiguously.
    size_t ob = brow * N_OUT;
    size_t total = (size_t)n_rows * N_OUT;
    #pragma unroll
    for (int i = 0; i < N_OUT; ++i) {
        size_t gi = ob + (size_t)(i * TPB + tid);
        if (gi < total) {
            int local = i * TPB + tid;   // 0..1791
            int r = local / N_OUT;
            int b = local - r * N_OUT;
            out[gi] = (float)((s_pos[r] >> (6 - b)) & 1);
        }
    }
}

extern "C" void kernel_launch(void* const* d_in, const int* in_sizes, int n_in,
                              void* d_out, int out_size) {
    const uint4* X = (const uint4*)d_in[0];
    float* out = (float*)d_out;
    int n_rows = in_sizes[0] / N_BITS;

    int blocks = (n_rows + TPB - 1) / TPB;
    lzd108_kernel<<<blocks, TPB>>>(X, out, n_rows);
}